// round 6
// baseline (speedup 1.0000x reference)
#include <cuda_runtime.h>
#include <cuda_bf16.h>

// Problem constants (fixed by setup_inputs)
constexpr int B  = 8;
constexpr int N  = 16384;
constexpr int G  = 128;
constexpr int NC = 11;          // N_CLASSES
constexpr float THRESH = 0.3f;  // REG_FG_THRESH

constexpr int BLK = 64;                    // threads per block
constexpr int ROWS_PER_BLOCK = 2 * BLK;    // 2 ROIs per thread
constexpr int BLOCKS_PER_BATCH = N / ROWS_PER_BLOCK;  // 128

// ---- packed f32x2 helpers (Blackwell sm_103a) ----
typedef unsigned long long ull;
__device__ __forceinline__ ull pk2(float lo, float hi) {
    ull r; asm("mov.b64 %0,{%1,%2};" : "=l"(r) : "f"(lo), "f"(hi)); return r;
}
__device__ __forceinline__ void upk2(ull v, float& lo, float& hi) {
    asm("mov.b64 {%0,%1},%2;" : "=f"(lo), "=f"(hi) : "l"(v));
}
__device__ __forceinline__ ull add2(ull a, ull b) {
    ull r; asm("add.rn.f32x2 %0,%1,%2;" : "=l"(r) : "l"(a), "l"(b)); return r;
}
__device__ __forceinline__ ull mul2(ull a, ull b) {
    ull r; asm("mul.rn.f32x2 %0,%1,%2;" : "=l"(r) : "l"(a), "l"(b)); return r;
}
__device__ __forceinline__ ull fma2(ull a, ull b, ull c) {
    ull r; asm("fma.rn.f32x2 %0,%1,%2,%3;" : "=l"(r) : "l"(a), "l"(b), "l"(c)); return r;
}

// Output layout (concatenated, float32):
//   [0,            B*N*7)   batch_rois
//   [B*N*7,        2*B*N*7) gt_of_rois
//   [2*B*N*7,      +B*N)    gt_label_of_rois (as float)
//   [2*B*N*7+B*N,  +B*N)    reg_valid_mask

struct RoiState {
    float r[7];
    float amin[3], amax[3];
    float va, C;     // C = (ra + rbmax + 0.5)^2 filter constant
    ull   ax2, ay2, az2;
};

__global__ __launch_bounds__(BLK)
void ptl_kernel(const float* __restrict__ rois,
                const float* __restrict__ gt,
                const int*   __restrict__ gt_lab,
                const float* __restrict__ assign_gt,
                const int*   __restrict__ assign_lab,
                float* __restrict__ out)
{
    // Shared GT cache for this batch.
    // Filter data, pair p covers boxes e=2p, o=2p+1:
    //   sCXY[p] = (-cx_e, -cx_o, -cy_e, -cy_o)   (one LDS.128)
    //   sCZ [2p..] = (-cz_e, -cz_o)              (one LDS.64)
    __shared__ float4 sCXY[G / 2];
    __shared__ float  sCZ[G];
    __shared__ float4 sMin[G];         // bmin.x, bmin.y, bmin.z, vol_b
    __shared__ float4 sMax[G];         // bmax.x, bmax.y, bmax.z, (pad)
    __shared__ float  sBox[G][8];      // cx cy cz dx dy dz (-h) label_bits
    __shared__ float  sRbMax[2];       // per-warp rb maxima

    const int tid   = threadIdx.x;                       // 0..63
    const int batch = blockIdx.x / BLOCKS_PER_BATCH;
    const int base  = (blockIdx.x % BLOCKS_PER_BATCH) * ROWS_PER_BLOCK;

    // GT preamble: 2 boxes per thread
    float rb_local = 0.f;
    #pragma unroll
    for (int rr = 0; rr < 2; ++rr) {
        const int g = tid + rr * BLK;
        const float* gp = gt + ((size_t)batch * G + g) * 7;
        float cx = gp[0], cy = gp[1], cz = gp[2];
        float dx = gp[3], dy = gp[4], dz = gp[5];
        float h  = gp[6];
        sMin[g] = make_float4(cx - 0.5f * dx, cy - 0.5f * dy, cz - 0.5f * dz,
                              dx * dy * dz);
        sMax[g] = make_float4(cx + 0.5f * dx, cy + 0.5f * dy, cz + 0.5f * dz, 0.f);
        sBox[g][0] = cx; sBox[g][1] = cy; sBox[g][2] = cz;
        sBox[g][3] = dx; sBox[g][4] = dy; sBox[g][5] = dz;
        sBox[g][6] = -h;  // heading multiplied by -1 per reference
        sBox[g][7] = __int_as_float(gt_lab[(size_t)batch * G + g]);

        const int p = g >> 1, lane = g & 1;
        float* pc = (float*)&sCXY[p];
        pc[0 + lane] = -cx;  pc[2 + lane] = -cy;
        sCZ[g] = -cz;

        rb_local = fmaxf(rb_local, 0.5f * sqrtf(dx * dx + dy * dy + dz * dz));
    }
    #pragma unroll
    for (int s = 16; s; s >>= 1)
        rb_local = fmaxf(rb_local, __shfl_xor_sync(0xffffffffu, rb_local, s));
    if ((tid & 31) == 0) sRbMax[tid >> 5] = rb_local;
    __syncthreads();
    const float rbmax = fmaxf(sRbMax[0], sRbMax[1]);

    // Load both ROIs for this thread (adjacent threads -> adjacent rows).
    RoiState st[2];
    size_t riv[2];
    #pragma unroll
    for (int q = 0; q < 2; ++q) {
        const int row = base + q * BLK + tid;
        const size_t ri = (size_t)batch * N + row;
        riv[q] = ri;
        const float* rp = rois + ri * 7;
        #pragma unroll
        for (int k = 0; k < 7; ++k) st[q].r[k] = rp[k];
        #pragma unroll
        for (int a = 0; a < 3; ++a) {
            st[q].amin[a] = st[q].r[a] - 0.5f * st[q].r[3 + a];
            st[q].amax[a] = st[q].r[a] + 0.5f * st[q].r[3 + a];
        }
        st[q].va = st[q].r[3] * st[q].r[4] * st[q].r[5];
        const float ra = 0.5f * sqrtf(st[q].r[3] * st[q].r[3] +
                                      st[q].r[4] * st[q].r[4] +
                                      st[q].r[5] * st[q].r[5]);
        // inter>0 => dsq < (ra+rb_g)^2 <= (ra+rbmax)^2 < C  (Cauchy-Schwarz;
        // +0.5 margin absorbs all fp rounding; '<=' keeps it conservative).
        const float Cr = ra + rbmax + 0.5f;
        st[q].C = Cr * Cr;
        st[q].ax2 = pk2(st[q].r[0], st[q].r[0]);
        st[q].ay2 = pk2(st[q].r[1], st[q].r[1]);
        st[q].az2 = pk2(st[q].r[2], st[q].r[2]);
    }

    // ---- Phase 1: packed sphere filter, 2 boxes/step, shared loads for 2 ROIs.
    // Zero-inter pairs can never win the strict-'>' argmax, so the
    // conservative filter is exactly lossless.
    unsigned mkA[4], mkB[4];
    #pragma unroll
    for (int c = 0; c < 4; ++c) {
        unsigned mA = 0, mB = 0;
        #pragma unroll
        for (int i = 0; i < 16; ++i) {
            const int p = c * 16 + i;
            const ulonglong2 qxy = *(const ulonglong2*)&sCXY[p];
            const ull qz = *(const ull*)&sCZ[2 * p];
            {   // ROI A
                const ull dx2 = add2(st[0].ax2, qxy.x);
                const ull dy2 = add2(st[0].ay2, qxy.y);
                const ull dz2 = add2(st[0].az2, qz);
                ull s2 = mul2(dx2, dx2);
                s2 = fma2(dy2, dy2, s2);
                s2 = fma2(dz2, dz2, s2);
                float s_lo, s_hi; upk2(s2, s_lo, s_hi);
                if (s_lo <= st[0].C) mA |= (1u << (2 * i));
                if (s_hi <= st[0].C) mA |= (1u << (2 * i + 1));
            }
            {   // ROI B (independent chain, same loads)
                const ull dx2 = add2(st[1].ax2, qxy.x);
                const ull dy2 = add2(st[1].ay2, qxy.y);
                const ull dz2 = add2(st[1].az2, qz);
                ull s2 = mul2(dx2, dx2);
                s2 = fma2(dy2, dy2, s2);
                s2 = fma2(dz2, dz2, s2);
                float s_lo, s_hi; upk2(s2, s_lo, s_hi);
                if (s_lo <= st[1].C) mB |= (1u << (2 * i));
                if (s_hi <= st[1].C) mB |= (1u << (2 * i + 1));
            }
        }
        mkA[c] = mA; mkB[c] = mB;
    }

    // ---- Phase 2 + epilogue per ROI ----
    float* o_rois = out;
    float* o_gt   = out + (size_t)B * N * 7;
    float* o_lab  = out + (size_t)B * N * 14;
    float* o_mask = o_lab + (size_t)B * N;

    #pragma unroll
    for (int q = 0; q < 2; ++q) {
        // iou = inter/(s-inter), s = va+vb, strictly monotone in inter/s
        // => argmax via cross-mult; strict '>' keeps first max (jnp.argmax).
        float bi = 0.f, bs = 1.f; int bg = 0;
        #pragma unroll
        for (int c = 0; c < 4; ++c) {
            unsigned m = q ? mkB[c] : mkA[c];
            while (m) {
                const int b = __ffs(m) - 1;
                m &= m - 1;
                const int g = c * 32 + b;
                const float4 mn = sMin[g];
                const float4 mx = sMax[g];
                float ox = fminf(st[q].amax[0], mx.x) - fmaxf(st[q].amin[0], mn.x);
                float oy = fminf(st[q].amax[1], mx.y) - fmaxf(st[q].amin[1], mn.y);
                float oz = fminf(st[q].amax[2], mx.z) - fmaxf(st[q].amin[2], mn.z);
                ox = fmaxf(ox, 0.0f);
                oy = fmaxf(oy, 0.0f);
                oz = fmaxf(oz, 0.0f);
                const float inter = ox * oy * oz;
                const float s     = st[q].va + mn.w;
                if (inter * bs > bi * s) { bi = inter; bs = s; bg = g; }
            }
        }

        const size_t ri = riv[q];
        const int  alab = assign_lab[ri];
        const bool pos1 = (alab >= 0);
        // max_ov >= THRESH  <=>  bi >= THRESH * clip(s - bi, 1e-6)
        const bool pos2 = (!pos1) && (bi >= THRESH * fmaxf(bs - bi, 1e-6f));

        const float* ag = assign_gt + ri * 7;

        #pragma unroll
        for (int k = 0; k < 7; ++k)
            o_rois[ri * 7 + k] = st[q].r[k];

        #pragma unroll
        for (int k = 0; k < 7; ++k) {
            float gv;
            if (pos1) {
                gv = ag[k];
                if (k == 6) gv = -gv;   // assign_gt heading negated per reference
            } else if (pos2) {
                gv = sBox[bg][k];       // heading already negated at store time
            } else {
                gv = 0.0f;              // must write: d_out is poisoned
            }
            o_gt[ri * 7 + k] = gv;
        }

        int lab = pos1 ? alab : (pos2 ? __float_as_int(sBox[bg][7]) : NC);
        o_lab[ri]  = (float)lab;
        o_mask[ri] = (pos1 || pos2) ? 1.0f : 0.0f;
    }
}

extern "C" void kernel_launch(void* const* d_in, const int* in_sizes, int n_in,
                              void* d_out, int out_size)
{
    const float* rois       = (const float*)d_in[0]; // [B,N,7]
    const float* gt         = (const float*)d_in[1]; // [B,G,7]
    const int*   gt_lab     = (const int*)  d_in[2]; // [B,G]
    const float* assign_gt  = (const float*)d_in[3]; // [B,N,7]
    const int*   assign_lab = (const int*)  d_in[4]; // [B,N]
    float*       out        = (float*)d_out;

    // 64 threads/block, 2 ROIs/thread -> 1024 blocks
    ptl_kernel<<<(B * N) / ROWS_PER_BLOCK, BLK>>>(rois, gt, gt_lab,
                                                  assign_gt, assign_lab, out);
}

// round 7
// speedup vs baseline: 1.1530x; 1.1530x over previous
#include <cuda_runtime.h>
#include <cuda_bf16.h>

// Problem constants (fixed by setup_inputs)
constexpr int B  = 8;
constexpr int N  = 16384;
constexpr int G  = 128;
constexpr int NC = 11;          // N_CLASSES
constexpr float THRESH = 0.3f;  // REG_FG_THRESH

// ---- packed f32x2 helpers (Blackwell sm_103a) ----
typedef unsigned long long ull;
__device__ __forceinline__ ull pk2(float lo, float hi) {
    ull r; asm("mov.b64 %0,{%1,%2};" : "=l"(r) : "f"(lo), "f"(hi)); return r;
}
__device__ __forceinline__ void upk2(ull v, float& lo, float& hi) {
    asm("mov.b64 {%0,%1},%2;" : "=f"(lo), "=f"(hi) : "l"(v));
}
__device__ __forceinline__ ull add2(ull a, ull b) {
    ull r; asm("add.rn.f32x2 %0,%1,%2;" : "=l"(r) : "l"(a), "l"(b)); return r;
}
__device__ __forceinline__ ull mul2(ull a, ull b) {
    ull r; asm("mul.rn.f32x2 %0,%1,%2;" : "=l"(r) : "l"(a), "l"(b)); return r;
}
__device__ __forceinline__ ull fma2(ull a, ull b, ull c) {
    ull r; asm("fma.rn.f32x2 %0,%1,%2,%3;" : "=l"(r) : "l"(a), "l"(b), "l"(c)); return r;
}

// Output layout (concatenated, float32):
//   [0,            B*N*7)   batch_rois
//   [B*N*7,        2*B*N*7) gt_of_rois
//   [2*B*N*7,      +B*N)    gt_label_of_rois (as float)
//   [2*B*N*7+B*N,  +B*N)    reg_valid_mask

__global__ __launch_bounds__(128)
void ptl_kernel(const float* __restrict__ rois,
                const float* __restrict__ gt,
                const int*   __restrict__ gt_lab,
                const float* __restrict__ assign_gt,
                const int*   __restrict__ assign_lab,
                float* __restrict__ out)
{
    // Shared GT cache for this batch.
    // Filter data, pair p covers boxes e=2p, o=2p+1:
    //   sCXY[p] = (-cx_e, -cx_o, -cy_e, -cy_o)   (one LDS.128)
    //   sCZ [2p..] = (-cz_e, -cz_o)              (one LDS.64)
    __shared__ float4 sCXY[G / 2];
    __shared__ float  sCZ[G];
    __shared__ float4 sMin[G];         // bmin.x, bmin.y, bmin.z, vol_b
    __shared__ float4 sMax[G];         // bmax.x, bmax.y, bmax.z, (pad)
    __shared__ float  sBox[G][8];      // cx cy cz dx dy dz (-h) label_bits
    __shared__ float  sRbMax[4];       // per-warp rb maxima

    const int tid   = threadIdx.x;           // 0..127
    const int batch = blockIdx.x >> 7;       // 128 blocks per batch
    const int row   = ((blockIdx.x & 127) << 7) + tid;

    {
        // one GT box per thread (G == blockDim)
        const float* gp = gt + ((size_t)batch * G + tid) * 7;
        float cx = gp[0], cy = gp[1], cz = gp[2];
        float dx = gp[3], dy = gp[4], dz = gp[5];
        float h  = gp[6];
        sMin[tid] = make_float4(cx - 0.5f * dx, cy - 0.5f * dy, cz - 0.5f * dz,
                                dx * dy * dz);
        sMax[tid] = make_float4(cx + 0.5f * dx, cy + 0.5f * dy, cz + 0.5f * dz, 0.f);
        sBox[tid][0] = cx; sBox[tid][1] = cy; sBox[tid][2] = cz;
        sBox[tid][3] = dx; sBox[tid][4] = dy; sBox[tid][5] = dz;
        sBox[tid][6] = -h;  // heading multiplied by -1 per reference
        sBox[tid][7] = __int_as_float(gt_lab[(size_t)batch * G + tid]);

        const int p = tid >> 1, lane = tid & 1;
        float* pc = (float*)&sCXY[p];
        pc[0 + lane] = -cx;  pc[2 + lane] = -cy;
        sCZ[tid] = -cz;

        // box half-diagonal; block max via warp shfl + cross-warp smem
        float rb = 0.5f * sqrtf(dx * dx + dy * dy + dz * dz);
        #pragma unroll
        for (int s = 16; s; s >>= 1)
            rb = fmaxf(rb, __shfl_xor_sync(0xffffffffu, rb, s));
        if ((tid & 31) == 0) sRbMax[tid >> 5] = rb;
    }
    __syncthreads();
    const float rbmax = fmaxf(fmaxf(sRbMax[0], sRbMax[1]),
                              fmaxf(sRbMax[2], sRbMax[3]));

    const size_t ri = (size_t)batch * N + row;
    const float* rp = rois + ri * 7;

    const float r0 = rp[0], r1 = rp[1], r2 = rp[2];
    const float r3 = rp[3], r4 = rp[4], r5 = rp[5];
    const float r6 = rp[6];

    const float aminx = r0 - 0.5f * r3, amaxx = r0 + 0.5f * r3;
    const float aminy = r1 - 0.5f * r4, amaxy = r1 + 0.5f * r4;
    const float aminz = r2 - 0.5f * r5, amaxz = r2 + 0.5f * r5;
    const float va = r3 * r4 * r5;
    const float ra = 0.5f * sqrtf(r3 * r3 + r4 * r4 + r5 * r5);

    // Filter constant: inter>0 => dsq < (ra+rb_g)^2 <= (ra+rbmax)^2 < C
    // (Cauchy-Schwarz). +0.5 margin absorbs all fp rounding; '<=' compare
    // keeps it conservative, so the filter is exactly lossless: zero-inter
    // pairs can never win the strict-'>' argmax.
    const float Cr = ra + rbmax + 0.5f;
    const float C  = Cr * Cr;

    const ull ax2 = pk2(r0, r0);
    const ull ay2 = pk2(r1, r1);
    const ull az2 = pk2(r2, r2);

    // ---- Phase 1: packed sphere filter, 2 boxes per step ----
    // Mask bits accumulated via explicit OR *tree* (not predicated RMW ORs):
    // all 16 iterations per chunk are independent dataflow, no serial chain.
    unsigned mk[4];
    #pragma unroll
    for (int c = 0; c < 4; ++c) {
        unsigned t[16];
        #pragma unroll
        for (int i = 0; i < 16; ++i) {
            const int p = c * 16 + i;
            const ulonglong2 qxy = *(const ulonglong2*)&sCXY[p];
            const ull qz = *(const ull*)&sCZ[2 * p];
            const ull dx2 = add2(ax2, qxy.x);
            const ull dy2 = add2(ay2, qxy.y);
            const ull dz2 = add2(az2, qz);
            ull s2 = mul2(dx2, dx2);
            s2 = fma2(dy2, dy2, s2);
            s2 = fma2(dz2, dz2, s2);
            float s_lo, s_hi;
            upk2(s2, s_lo, s_hi);
            t[i] = (s_lo <= C ? (1u << (2 * i)) : 0u)
                 | (s_hi <= C ? (2u << (2 * i)) : 0u);
        }
        // binary OR tree, depth 4
        #pragma unroll
        for (int stp = 1; stp < 16; stp <<= 1)
            #pragma unroll
            for (int i = 0; i < 16; i += 2 * stp)
                t[i] |= t[i + stp];
        mk[c] = t[0];
    }

    // ---- Phase 2: exact IoU-argmax over survivors (ascending g order) ----
    // iou = inter/(s - inter), s = va + vb, strictly monotone in inter/s
    // => argmax via cross-mult compare; strict '>' keeps first max (jnp.argmax).
    float bi = 0.f, bs = 1.f; int bg = 0;
    #pragma unroll
    for (int c = 0; c < 4; ++c) {
        unsigned m = mk[c];
        while (m) {
            const int b = __ffs(m) - 1;
            m &= m - 1;
            const int g = c * 32 + b;
            const float4 mn = sMin[g];
            const float4 mx = sMax[g];
            float ox = fminf(amaxx, mx.x) - fmaxf(aminx, mn.x);
            float oy = fminf(amaxy, mx.y) - fmaxf(aminy, mn.y);
            float oz = fminf(amaxz, mx.z) - fmaxf(aminz, mn.z);
            ox = fmaxf(ox, 0.0f);
            oy = fmaxf(oy, 0.0f);
            oz = fmaxf(oz, 0.0f);
            const float inter = ox * oy * oz;
            const float s     = va + mn.w;
            if (inter * bs > bi * s) { bi = inter; bs = s; bg = g; }
        }
    }

    const int  alab = assign_lab[ri];
    const bool pos1 = (alab >= 0);
    // max_ov >= THRESH  <=>  bi >= THRESH * clip(s - bi, 1e-6)
    const bool pos2 = (!pos1) && (bi >= THRESH * fmaxf(bs - bi, 1e-6f));

    float* o_rois = out;
    float* o_gt   = out + (size_t)B * N * 7;
    float* o_lab  = out + (size_t)B * N * 14;
    float* o_mask = o_lab + (size_t)B * N;

    const float* ag = assign_gt + ri * 7;

    // rois passthrough
    o_rois[ri * 7 + 0] = r0; o_rois[ri * 7 + 1] = r1; o_rois[ri * 7 + 2] = r2;
    o_rois[ri * 7 + 3] = r3; o_rois[ri * 7 + 4] = r4; o_rois[ri * 7 + 5] = r5;
    o_rois[ri * 7 + 6] = r6;

    #pragma unroll
    for (int k = 0; k < 7; ++k) {
        float gv;
        if (pos1) {
            gv = ag[k];
            if (k == 6) gv = -gv;   // assign_gt heading negated per reference
        } else if (pos2) {
            gv = sBox[bg][k];       // heading already negated at store time
        } else {
            gv = 0.0f;              // must write: d_out is poisoned
        }
        o_gt[ri * 7 + k] = gv;
    }

    int lab = pos1 ? alab : (pos2 ? __float_as_int(sBox[bg][7]) : NC);
    o_lab[ri]  = (float)lab;
    o_mask[ri] = (pos1 || pos2) ? 1.0f : 0.0f;
}

extern "C" void kernel_launch(void* const* d_in, const int* in_sizes, int n_in,
                              void* d_out, int out_size)
{
    const float* rois       = (const float*)d_in[0]; // [B,N,7]
    const float* gt         = (const float*)d_in[1]; // [B,G,7]
    const int*   gt_lab     = (const int*)  d_in[2]; // [B,G]
    const float* assign_gt  = (const float*)d_in[3]; // [B,N,7]
    const int*   assign_lab = (const int*)  d_in[4]; // [B,N]
    float*       out        = (float*)d_out;

    // B*N threads, 128 per block; 128 blocks per batch
    ptl_kernel<<<(B * N) / 128, 128>>>(rois, gt, gt_lab, assign_gt, assign_lab, out);
}